// round 12
// baseline (speedup 1.0000x reference)
#include <cuda_runtime.h>
#include <cuda_bf16.h>
#include <cstdint>

// Problem constants
#define NCLS   100
#define DDIM   10000
#define NROW   16384
#define MC     64           // rows per CTA (gemm) -> grid 256, 2 CTAs/SM
#define NC     112          // classes padded for 14 n8-tiles
#define KC     64           // K chunk (bf16)
#define NCH    157          // ceil(10000/64)
#define KPAD   (NCH * KC)   // 10048
#define G_CH    512         // gather cols per chunk (256 thr x float2)
#define G_NCHK  20          // ceil(10000/512)
#define LTILE   2048        // gather smem list tile
#define GATHER_SMEM 49152   // 8KB list + padding to cap occupancy at 4 CTAs/SM

// ---------------- device scratch ----------------
__device__ __nv_bfloat16 g_Bhi[NC * KPAD];
__device__ __nv_bfloat16 g_Blo[NC * KPAD];
__device__ int   g_pair[NROW];          // (tgt | pred<<8) if misclassified else -1
__device__ int   g_tgt[NROW];
__device__ int   g_is64;
__device__ int   g_list[2 * NROW];      // row lists: [side 0: by target][side 1: by pred]
__device__ int   g_clsoff[2 * NCLS];
__device__ int   g_clscnt[2 * NCLS];
__device__ float g_part[2 * NCLS * DDIM];   // [side][cls][col]

// gemm smem: A stage s at s*16384 (hi +0, lo +8192); B at 32768 + s*28672
#define GEMM_SMEM 90112

// ---------------- asm helpers ----------------
__device__ __forceinline__ uint32_t cvta_s(const void* p) {
    uint32_t a;
    asm("{ .reg .u64 t; cvta.to.shared.u64 t, %1; cvt.u32.u64 %0, t; }" : "=r"(a) : "l"(p));
    return a;
}
__device__ __forceinline__ void ldsm4(uint32_t* r, uint32_t a) {
    asm volatile("ldmatrix.sync.aligned.m8n8.x4.shared.b16 {%0,%1,%2,%3}, [%4];"
                 : "=r"(r[0]), "=r"(r[1]), "=r"(r[2]), "=r"(r[3]) : "r"(a));
}
__device__ __forceinline__ void ldsm2(uint32_t* r, uint32_t a) {
    asm volatile("ldmatrix.sync.aligned.m8n8.x2.shared.b16 {%0,%1}, [%2];"
                 : "=r"(r[0]), "=r"(r[1]) : "r"(a));
}
__device__ __forceinline__ void mma16816(float* d, const uint32_t* a, const uint32_t* b) {
    asm volatile(
        "mma.sync.aligned.m16n8k16.row.col.f32.bf16.bf16.f32 "
        "{%0,%1,%2,%3}, {%4,%5,%6,%7}, {%8,%9}, {%0,%1,%2,%3};"
        : "+f"(d[0]), "+f"(d[1]), "+f"(d[2]), "+f"(d[3])
        : "r"(a[0]), "r"(a[1]), "r"(a[2]), "r"(a[3]), "r"(b[0]), "r"(b[1]));
}
__device__ __forceinline__ void cpasync16(uint32_t dst, const void* src) {
    asm volatile("cp.async.cg.shared.global [%0], [%1], 16;" :: "r"(dst), "l"(src));
}
__device__ __forceinline__ void cp_commit() { asm volatile("cp.async.commit_group;"); }
__device__ __forceinline__ void cp_wait0()  { asm volatile("cp.async.wait_group 0;"); }

__device__ __forceinline__ uint2 split_pack(float4 f, uint2& lo) {
    __nv_bfloat162 h01 = __floats2bfloat162_rn(f.x, f.y);
    __nv_bfloat162 h23 = __floats2bfloat162_rn(f.z, f.w);
    __nv_bfloat162 l01 = __floats2bfloat162_rn(f.x - __low2float(h01), f.y - __high2float(h01));
    __nv_bfloat162 l23 = __floats2bfloat162_rn(f.z - __low2float(h23), f.w - __high2float(h23));
    uint2 hi;
    hi.x = *reinterpret_cast<uint32_t*>(&h01);
    hi.y = *reinterpret_cast<uint32_t*>(&h23);
    lo.x = *reinterpret_cast<uint32_t*>(&l01);
    lo.y = *reinterpret_cast<uint32_t*>(&l23);
    return hi;
}

// ================= kernel 0a/0b: canonicalize targets =================
__global__ void detect_tgt_kernel(const int* __restrict__ t32) {
    __shared__ int any_nonzero;
    if (threadIdx.x == 0) any_nonzero = 0;
    __syncthreads();
    if (t32[2 * threadIdx.x + 1] != 0) atomicOr(&any_nonzero, 1);
    __syncthreads();
    if (threadIdx.x == 0) g_is64 = any_nonzero ? 0 : 1;
}
__global__ void conv_tgt_kernel(const int* __restrict__ t32) {
    const int i = blockIdx.x * blockDim.x + threadIdx.x;
    if (i < NROW) g_tgt[i] = g_is64 ? t32[2 * i] : t32[i];
}

// ================= kernel 1: split class_hvs into bf16 hi/lo =================
__global__ void prep_b_kernel(const float* __restrict__ ch) {
    int idx = blockIdx.x * blockDim.x + threadIdx.x;
    if (idx >= NC * KPAD) return;
    int row = idx / KPAD, col = idx - row * KPAD;
    float v = (row < NCLS && col < DDIM) ? ch[row * DDIM + col] : 0.0f;
    __nv_bfloat16 hi = __float2bfloat16_rn(v);
    g_Bhi[idx] = hi;
    g_Blo[idx] = __float2bfloat16_rn(v - __bfloat162float(hi));
}

// ================= kernel 2: split-bf16 3-GEMM, M=64, 2Mx2Nx2K, 2 CTAs/SM =========
__global__ __launch_bounds__(256, 2)
void gemm_kernel(const float* __restrict__ enc,
                 float* __restrict__ out_scores) {
    extern __shared__ __align__(128) char smem[];
    const uint32_t sb = cvta_s(smem);
    const int tid = threadIdx.x, lane = tid & 31, wid = tid >> 5;
    const int warpM = wid >> 2;          // 0..1 : 32 rows each
    const int warpN = (wid >> 1) & 1;    // 0..1 : 56 cols each
    const int warpK = wid & 1;           // 0..1 : ksteps {2k, 2k+1}
    const int r0 = blockIdx.x * MC;

    uint32_t aoff[2][2];
    #pragma unroll
    for (int mi = 0; mi < 2; mi++) {
        const int row = warpM * 32 + mi * 16 + (lane & 15);
        const int cl = lane >> 4;
        #pragma unroll
        for (int j = 0; j < 2; j++) {
            const int ks = warpK * 2 + j;
            aoff[mi][j] = row * 128 + (((ks * 2 + cl) ^ (row & 7)) * 16);
        }
    }
    uint32_t boff[3][2], b2off[2];
    #pragma unroll
    for (int t = 0; t < 3; t++) {
        const int row = warpN * 56 + t * 16 + (lane & 7) + ((lane >> 4) & 1) * 8;
        const int cl = (lane >> 3) & 1;
        #pragma unroll
        for (int j = 0; j < 2; j++) {
            const int ks = warpK * 2 + j;
            boff[t][j] = row * 128 + (((ks * 2 + cl) ^ (row & 7)) * 16);
        }
    }
    {
        const int row = warpN * 56 + 48 + (lane & 7);
        const int cl = (lane >> 3) & 1;
        #pragma unroll
        for (int j = 0; j < 2; j++) {
            const int ks = warpK * 2 + j;
            b2off[j] = row * 128 + (((ks * 2 + cl) ^ (row & 7)) * 16);
        }
    }

    // A: 64 rows x 64 cols, 4 float4 per thread
    const int aRow = tid >> 2;
    const int aCol0 = (tid & 3) * 16;
    const float* aptr = enc + (size_t)(r0 + aRow) * DDIM + aCol0;
    uint32_t asw[4];
    #pragma unroll
    for (int j = 0; j < 4; j++) {
        const int byte = aCol0 * 2 + j * 8;
        asw[j] = aRow * 128 + (byte ^ ((aRow & 7) << 4));
    }

    const __nv_bfloat16* bsrc[7];
    uint32_t bdstrel[7];
    #pragma unroll
    for (int q = 0; q < 7; q++) {
        const int cid = tid + q * 256;
        const int half = cid / 896;
        const int rem = cid - half * 896;
        const int brow = rem >> 3, bc = rem & 7;
        bsrc[q] = (half ? g_Blo : g_Bhi) + (size_t)brow * KPAD + bc * 8;
        bdstrel[q] = half * 14336 + brow * 128 + ((bc ^ (brow & 7)) * 16);
    }

    float d[2][7][4];
    #pragma unroll
    for (int mi = 0; mi < 2; mi++)
        #pragma unroll
        for (int ni = 0; ni < 7; ni++)
            #pragma unroll
            for (int r = 0; r < 4; r++) d[mi][ni][r] = 0.0f;

    float4 pf[4];

    #pragma unroll
    for (int j = 0; j < 4; j++) {
        const int gcol = aCol0 + j * 4;
        pf[j] = (gcol < DDIM) ? *(const float4*)(aptr + j * 4)
                              : make_float4(0.f, 0.f, 0.f, 0.f);
    }
    #pragma unroll
    for (int j = 0; j < 4; j++) {
        uint2 lo; uint2 hi = split_pack(pf[j], lo);
        *(uint2*)(smem + asw[j]) = hi;
        *(uint2*)(smem + 8192 + asw[j]) = lo;
    }
    #pragma unroll
    for (int q = 0; q < 7; q++)
        cpasync16(sb + 32768 + bdstrel[q], bsrc[q]);
    cp_commit();
    cp_wait0();
    __syncthreads();

    for (int i = 0; i < NCH; i++) {
        const int s = i & 1;
        if (i + 1 < NCH) {
            const int k0 = (i + 1) * KC;
            #pragma unroll
            for (int j = 0; j < 4; j++) {
                const int gcol = k0 + aCol0 + j * 4;
                pf[j] = (gcol < DDIM) ? *(const float4*)(aptr + k0 + j * 4)
                                      : make_float4(0.f, 0.f, 0.f, 0.f);
            }
            const uint32_t bb = sb + 32768 + (s ^ 1) * 28672;
            #pragma unroll
            for (int q = 0; q < 7; q++)
                cpasync16(bb + bdstrel[q], bsrc[q] + k0);
            cp_commit();
        }

        const uint32_t abase = sb + s * 16384;
        const uint32_t bbase = sb + 32768 + s * 28672;
        #pragma unroll
        for (int j = 0; j < 2; j++) {
            uint32_t ah[2][4], al[2][4], bh[7][2], bl[7][2];
            #pragma unroll
            for (int mi = 0; mi < 2; mi++) {
                ldsm4(ah[mi], abase + aoff[mi][j]);
                ldsm4(al[mi], abase + 8192 + aoff[mi][j]);
            }
            #pragma unroll
            for (int t = 0; t < 3; t++) {
                ldsm4(&bh[2 * t][0], bbase + boff[t][j]);
                ldsm4(&bl[2 * t][0], bbase + 14336 + boff[t][j]);
            }
            ldsm2(bh[6], bbase + b2off[j]);
            ldsm2(bl[6], bbase + 14336 + b2off[j]);

            #pragma unroll
            for (int mi = 0; mi < 2; mi++)
                #pragma unroll
                for (int ni = 0; ni < 7; ni++) {
                    mma16816(d[mi][ni], ah[mi], bh[ni]);
                    mma16816(d[mi][ni], ah[mi], bl[ni]);
                    mma16816(d[mi][ni], al[mi], bh[ni]);
                }
        }

        if (i + 1 < NCH) {
            const int s2 = (s ^ 1) * 16384;
            #pragma unroll
            for (int j = 0; j < 4; j++) {
                uint2 lo; uint2 hi = split_pack(pf[j], lo);
                *(uint2*)(smem + s2 + asw[j]) = hi;
                *(uint2*)(smem + s2 + 8192 + asw[j]) = lo;
            }
            cp_wait0();
        }
        __syncthreads();
    }

    // ---- epilogue: K-partial reduce through smem tile, scores + argmax + pair ----
    float* tile = (float*)smem;
    if (warpK == 0) {
        #pragma unroll
        for (int mi = 0; mi < 2; mi++)
            #pragma unroll
            for (int ni = 0; ni < 7; ni++)
                #pragma unroll
                for (int r = 0; r < 4; r++) {
                    const int row = warpM * 32 + mi * 16 + (lane >> 2) + (r >= 2 ? 8 : 0);
                    const int col = warpN * 56 + ni * 8 + (lane & 3) * 2 + (r & 1);
                    tile[row * 113 + col] = d[mi][ni][r];
                }
    }
    __syncthreads();
    if (warpK == 1) {
        #pragma unroll
        for (int mi = 0; mi < 2; mi++)
            #pragma unroll
            for (int ni = 0; ni < 7; ni++)
                #pragma unroll
                for (int r = 0; r < 4; r++) {
                    const int row = warpM * 32 + mi * 16 + (lane >> 2) + (r >= 2 ? 8 : 0);
                    const int col = warpN * 56 + ni * 8 + (lane & 3) * 2 + (r & 1);
                    tile[row * 113 + col] += d[mi][ni][r];
                }
    }
    __syncthreads();

    for (int idx = tid; idx < MC * NCLS; idx += 256) {
        const int r = idx / NCLS, c = idx - r * NCLS;
        out_scores[(size_t)(r0 + r) * NCLS + c] = tile[r * 113 + c];
    }
    if (tid < MC) {
        const int r = tid;
        float best = tile[r * 113];
        int bi = 0;
        #pragma unroll 4
        for (int c = 1; c < NCLS; c++) {
            const float v = tile[r * 113 + c];
            if (v > best) { best = v; bi = c; }
        }
        const int tg = g_tgt[r0 + r];
        g_pair[r0 + r] = (tg != bi) ? (tg | (bi << 8)) : -1;
    }
}

// ================= kernel 3a: build per-class row lists (1 CTA, deterministic) ======
__global__ __launch_bounds__(256)
void build_kernel() {
    __shared__ int scnt[32][2][NCLS];      // 25600 B
    __shared__ int s_off[2][NCLS];
    __shared__ int s_tot[2][NCLS];
    const int t = threadIdx.x;

    for (int i = t; i < 32 * 2 * NCLS; i += 256) ((int*)scnt)[i] = 0;
    __syncthreads();

    if (t < 32) {
        const int rb = t * 512;
        #pragma unroll 8
        for (int j = 0; j < 512; j++) {
            const int pr = g_pair[rb + j];
            if (pr >= 0) {
                scnt[t][0][pr & 0xFF]++;
                scnt[t][1][(pr >> 8) & 0xFF]++;
            }
        }
    }
    __syncthreads();

    if (t < 2 * NCLS) {
        const int side = t / NCLS, c = t - side * NCLS;
        int run = 0;
        #pragma unroll 4
        for (int s = 0; s < 32; s++) {
            const int v = scnt[s][side][c];
            scnt[s][side][c] = run;
            run += v;
        }
        s_tot[side][c] = run;
    }
    __syncthreads();

    if (t < 2) {
        int run = 0;
        for (int c = 0; c < NCLS; c++) { s_off[t][c] = run; run += s_tot[t][c]; }
    }
    __syncthreads();

    if (t < 2 * NCLS) {
        const int side = t / NCLS, c = t - side * NCLS;
        const int o = s_off[side][c];
        #pragma unroll 4
        for (int s = 0; s < 32; s++) scnt[s][side][c] += o;
        g_clsoff[t] = o;
        g_clscnt[t] = s_tot[side][c];
    }
    __syncthreads();

    if (t < 32) {
        const int rb = t * 512;
        for (int j = 0; j < 512; j++) {
            const int r = rb + j;
            const int pr = g_pair[r];
            if (pr >= 0) {
                g_list[scnt[t][0][pr & 0xFF]++] = r;
                g_list[NROW + scnt[t][1][(pr >> 8) & 0xFF]++] = r;
            }
        }
    }
}

// ================= kernel 3b: gather-accumulate, L2-resident slices ================
// blockIdx.x = (cls, side)  (200 CTAs per chunk, sharing one 33.5MB column slice)
// blockIdx.y = chunk        (20 chunks of 512 cols)
// 48KB dummy smem caps occupancy at 4 CTAs/SM -> ~3 slices resident (~100MB < L2).
__global__ __launch_bounds__(256)
void gather_kernel(const float* __restrict__ enc) {
    extern __shared__ int sdyn[];
    int* slist = sdyn;                  // first LTILE ints used
    const int rest = blockIdx.x;        // 0..199
    const int cls = rest % NCLS;
    const int side = rest / NCLS;
    const int chunk = blockIdx.y;
    const int t = threadIdx.x;

    const int n = g_clscnt[side * NCLS + cls];
    const int base = g_clsoff[side * NCLS + cls];
    const int* list = g_list + side * NROW + base;
    const int c0 = chunk * G_CH + 2 * t;      // even; pairs never straddle DDIM
    const bool ok = c0 < DDIM;

    float2 acc = make_float2(0.f, 0.f);

    for (int tb = 0; tb < n; tb += LTILE) {
        const int m = (n - tb < LTILE) ? (n - tb) : LTILE;
        __syncthreads();
        for (int i = t; i < m; i += 256) slist[i] = list[tb + i];
        __syncthreads();

        int i = 0;
        for (; i + 8 <= m; i += 8) {
            int r[8];
            #pragma unroll
            for (int u = 0; u < 8; u++) r[u] = slist[i + u];
            if (ok) {
                #pragma unroll
                for (int u = 0; u < 8; u++) {
                    const float2 v = *(const float2*)(enc + (size_t)r[u] * DDIM + c0);
                    acc.x += v.x; acc.y += v.y;
                }
            }
        }
        for (; i < m; i++) {
            if (ok) {
                const float2 v = *(const float2*)(enc + (size_t)slist[i] * DDIM + c0);
                acc.x += v.x; acc.y += v.y;
            }
        }
    }

    if (ok)
        *(float2*)(g_part + (size_t)(side * NCLS + cls) * DDIM + c0) = acc;
}

// ================= kernel 4: clip + update =================
__global__ void finalize_kernel(const float* __restrict__ ch, float* __restrict__ out2) {
    int i = blockIdx.x * blockDim.x + threadIdx.x;
    if (i >= NCLS * DDIM) return;
    float a = g_part[i];
    float s = g_part[NCLS * DDIM + i];
    a = fminf(fmaxf(a, -1.0f), 1.0f);
    s = fminf(fmaxf(s, -1.0f), 1.0f);
    out2[i] = ch[i] + a - s;
}

// ================= launch =================
extern "C" void kernel_launch(void* const* d_in, const int* in_sizes, int n_in,
                              void* d_out, int out_size) {
    (void)in_sizes; (void)n_in; (void)out_size;
    const float* enc = (const float*)d_in[0];
    const int* tgt32 = (const int*)d_in[1];
    const float* ch = (const float*)d_in[2];
    float* out = (float*)d_out;
    float* out_scores = out;                       // [N, NCLS]
    float* out_hvs = out + (size_t)NROW * NCLS;    // [NCLS, DDIM]

    cudaFuncSetAttribute(gemm_kernel, cudaFuncAttributeMaxDynamicSharedMemorySize, GEMM_SMEM);

    detect_tgt_kernel<<<1, 256>>>(tgt32);
    conv_tgt_kernel<<<(NROW + 255) / 256, 256>>>(tgt32);
    prep_b_kernel<<<(NC * KPAD + 255) / 256, 256>>>(ch);
    gemm_kernel<<<NROW / MC, 256, GEMM_SMEM>>>(enc, out_scores);
    build_kernel<<<1, 256>>>();
    gather_kernel<<<dim3(2 * NCLS, G_NCHK), 256, GATHER_SMEM>>>(enc);
    finalize_kernel<<<(NCLS * DDIM + 255) / 256, 256>>>(ch, out_hvs);
}

// round 15
// speedup vs baseline: 1.0486x; 1.0486x over previous
#include <cuda_runtime.h>
#include <cuda_bf16.h>
#include <cstdint>

// Problem constants
#define NCLS   100
#define DDIM   10000
#define NROW   16384
#define MC     64           // rows per CTA (gemm) -> grid 256, 2 CTAs/SM
#define NC     112          // classes padded for 14 n8-tiles
#define KC     64           // K chunk (bf16)
#define NCH    157          // ceil(10000/64)
#define KPAD   (NCH * KC)   // 10048
#define CH_COLS 1280        // gather cols per chunk (256 thr x 5)
#define NCHK    8           // 8*1280 = 10240 >= 10000
#define LTILE   2048        // gather smem list tile

// ---------------- device scratch ----------------
__device__ __nv_bfloat16 g_Bhi[NC * KPAD];
__device__ __nv_bfloat16 g_Blo[NC * KPAD];
__device__ int   g_pair[NROW];          // (tgt | pred<<8) if misclassified else -1
__device__ int   g_tgt[NROW];
__device__ int   g_is64;
__device__ int   g_list[2 * NROW];      // row lists: [side 0: by target][side 1: by pred]
__device__ int   g_clsoff[2 * NCLS];
__device__ int   g_clscnt[2 * NCLS];
__device__ float g_part[2 * NCLS * DDIM];   // [side][cls][col]

// gemm smem: A stage s at s*16384 (hi +0, lo +8192); B at 32768 + s*28672
#define GEMM_SMEM 90112

// ---------------- asm helpers ----------------
__device__ __forceinline__ uint32_t cvta_s(const void* p) {
    uint32_t a;
    asm("{ .reg .u64 t; cvta.to.shared.u64 t, %1; cvt.u32.u64 %0, t; }" : "=r"(a) : "l"(p));
    return a;
}
__device__ __forceinline__ void ldsm4(uint32_t* r, uint32_t a) {
    asm volatile("ldmatrix.sync.aligned.m8n8.x4.shared.b16 {%0,%1,%2,%3}, [%4];"
                 : "=r"(r[0]), "=r"(r[1]), "=r"(r[2]), "=r"(r[3]) : "r"(a));
}
__device__ __forceinline__ void ldsm2(uint32_t* r, uint32_t a) {
    asm volatile("ldmatrix.sync.aligned.m8n8.x2.shared.b16 {%0,%1}, [%2];"
                 : "=r"(r[0]), "=r"(r[1]) : "r"(a));
}
__device__ __forceinline__ void mma16816(float* d, const uint32_t* a, const uint32_t* b) {
    asm volatile(
        "mma.sync.aligned.m16n8k16.row.col.f32.bf16.bf16.f32 "
        "{%0,%1,%2,%3}, {%4,%5,%6,%7}, {%8,%9}, {%0,%1,%2,%3};"
        : "+f"(d[0]), "+f"(d[1]), "+f"(d[2]), "+f"(d[3])
        : "r"(a[0]), "r"(a[1]), "r"(a[2]), "r"(a[3]), "r"(b[0]), "r"(b[1]));
}
__device__ __forceinline__ void cpasync16(uint32_t dst, const void* src) {
    asm volatile("cp.async.cg.shared.global [%0], [%1], 16;" :: "r"(dst), "l"(src));
}
__device__ __forceinline__ void cp_commit() { asm volatile("cp.async.commit_group;"); }
__device__ __forceinline__ void cp_wait0()  { asm volatile("cp.async.wait_group 0;"); }

__device__ __forceinline__ uint2 split_pack(float4 f, uint2& lo) {
    __nv_bfloat162 h01 = __floats2bfloat162_rn(f.x, f.y);
    __nv_bfloat162 h23 = __floats2bfloat162_rn(f.z, f.w);
    __nv_bfloat162 l01 = __floats2bfloat162_rn(f.x - __low2float(h01), f.y - __high2float(h01));
    __nv_bfloat162 l23 = __floats2bfloat162_rn(f.z - __low2float(h23), f.w - __high2float(h23));
    uint2 hi;
    hi.x = *reinterpret_cast<uint32_t*>(&h01);
    hi.y = *reinterpret_cast<uint32_t*>(&h23);
    lo.x = *reinterpret_cast<uint32_t*>(&l01);
    lo.y = *reinterpret_cast<uint32_t*>(&l23);
    return hi;
}

// ================= kernel 0a/0b: canonicalize targets =================
__global__ void detect_tgt_kernel(const int* __restrict__ t32) {
    __shared__ int any_nonzero;
    if (threadIdx.x == 0) any_nonzero = 0;
    __syncthreads();
    if (t32[2 * threadIdx.x + 1] != 0) atomicOr(&any_nonzero, 1);
    __syncthreads();
    if (threadIdx.x == 0) g_is64 = any_nonzero ? 0 : 1;
}
__global__ void conv_tgt_kernel(const int* __restrict__ t32) {
    const int i = blockIdx.x * blockDim.x + threadIdx.x;
    if (i < NROW) g_tgt[i] = g_is64 ? t32[2 * i] : t32[i];
}

// ================= kernel 1: split class_hvs into bf16 hi/lo =================
__global__ void prep_b_kernel(const float* __restrict__ ch) {
    int idx = blockIdx.x * blockDim.x + threadIdx.x;
    if (idx >= NC * KPAD) return;
    int row = idx / KPAD, col = idx - row * KPAD;
    float v = (row < NCLS && col < DDIM) ? ch[row * DDIM + col] : 0.0f;
    __nv_bfloat16 hi = __float2bfloat16_rn(v);
    g_Bhi[idx] = hi;
    g_Blo[idx] = __float2bfloat16_rn(v - __bfloat162float(hi));
}

// ================= kernel 2: split-bf16 3-GEMM, M=64, 2Mx2Nx2K, 2 CTAs/SM =========
__global__ __launch_bounds__(256, 2)
void gemm_kernel(const float* __restrict__ enc,
                 float* __restrict__ out_scores) {
    extern __shared__ __align__(128) char smem[];
    const uint32_t sb = cvta_s(smem);
    const int tid = threadIdx.x, lane = tid & 31, wid = tid >> 5;
    const int warpM = wid >> 2;          // 0..1 : 32 rows each
    const int warpN = (wid >> 1) & 1;    // 0..1 : 56 cols each
    const int warpK = wid & 1;           // 0..1 : ksteps {2k, 2k+1}
    const int r0 = blockIdx.x * MC;

    uint32_t aoff[2][2];
    #pragma unroll
    for (int mi = 0; mi < 2; mi++) {
        const int row = warpM * 32 + mi * 16 + (lane & 15);
        const int cl = lane >> 4;
        #pragma unroll
        for (int j = 0; j < 2; j++) {
            const int ks = warpK * 2 + j;
            aoff[mi][j] = row * 128 + (((ks * 2 + cl) ^ (row & 7)) * 16);
        }
    }
    uint32_t boff[3][2], b2off[2];
    #pragma unroll
    for (int t = 0; t < 3; t++) {
        const int row = warpN * 56 + t * 16 + (lane & 7) + ((lane >> 4) & 1) * 8;
        const int cl = (lane >> 3) & 1;
        #pragma unroll
        for (int j = 0; j < 2; j++) {
            const int ks = warpK * 2 + j;
            boff[t][j] = row * 128 + (((ks * 2 + cl) ^ (row & 7)) * 16);
        }
    }
    {
        const int row = warpN * 56 + 48 + (lane & 7);
        const int cl = (lane >> 3) & 1;
        #pragma unroll
        for (int j = 0; j < 2; j++) {
            const int ks = warpK * 2 + j;
            b2off[j] = row * 128 + (((ks * 2 + cl) ^ (row & 7)) * 16);
        }
    }

    // A: 64 rows x 64 cols, 4 float4 per thread
    const int aRow = tid >> 2;
    const int aCol0 = (tid & 3) * 16;
    const float* aptr = enc + (size_t)(r0 + aRow) * DDIM + aCol0;
    uint32_t asw[4];
    #pragma unroll
    for (int j = 0; j < 4; j++) {
        const int byte = aCol0 * 2 + j * 8;
        asw[j] = aRow * 128 + (byte ^ ((aRow & 7) << 4));
    }

    const __nv_bfloat16* bsrc[7];
    uint32_t bdstrel[7];
    #pragma unroll
    for (int q = 0; q < 7; q++) {
        const int cid = tid + q * 256;
        const int half = cid / 896;
        const int rem = cid - half * 896;
        const int brow = rem >> 3, bc = rem & 7;
        bsrc[q] = (half ? g_Blo : g_Bhi) + (size_t)brow * KPAD + bc * 8;
        bdstrel[q] = half * 14336 + brow * 128 + ((bc ^ (brow & 7)) * 16);
    }

    float d[2][7][4];
    #pragma unroll
    for (int mi = 0; mi < 2; mi++)
        #pragma unroll
        for (int ni = 0; ni < 7; ni++)
            #pragma unroll
            for (int r = 0; r < 4; r++) d[mi][ni][r] = 0.0f;

    float4 pf[4];

    #pragma unroll
    for (int j = 0; j < 4; j++) {
        const int gcol = aCol0 + j * 4;
        pf[j] = (gcol < DDIM) ? *(const float4*)(aptr + j * 4)
                              : make_float4(0.f, 0.f, 0.f, 0.f);
    }
    #pragma unroll
    for (int j = 0; j < 4; j++) {
        uint2 lo; uint2 hi = split_pack(pf[j], lo);
        *(uint2*)(smem + asw[j]) = hi;
        *(uint2*)(smem + 8192 + asw[j]) = lo;
    }
    #pragma unroll
    for (int q = 0; q < 7; q++)
        cpasync16(sb + 32768 + bdstrel[q], bsrc[q]);
    cp_commit();
    cp_wait0();
    __syncthreads();

    for (int i = 0; i < NCH; i++) {
        const int s = i & 1;
        if (i + 1 < NCH) {
            const int k0 = (i + 1) * KC;
            #pragma unroll
            for (int j = 0; j < 4; j++) {
                const int gcol = k0 + aCol0 + j * 4;
                pf[j] = (gcol < DDIM) ? *(const float4*)(aptr + k0 + j * 4)
                                      : make_float4(0.f, 0.f, 0.f, 0.f);
            }
            const uint32_t bb = sb + 32768 + (s ^ 1) * 28672;
            #pragma unroll
            for (int q = 0; q < 7; q++)
                cpasync16(bb + bdstrel[q], bsrc[q] + k0);
            cp_commit();
        }

        const uint32_t abase = sb + s * 16384;
        const uint32_t bbase = sb + 32768 + s * 28672;
        #pragma unroll
        for (int j = 0; j < 2; j++) {
            uint32_t ah[2][4], al[2][4], bh[7][2], bl[7][2];
            #pragma unroll
            for (int mi = 0; mi < 2; mi++) {
                ldsm4(ah[mi], abase + aoff[mi][j]);
                ldsm4(al[mi], abase + 8192 + aoff[mi][j]);
            }
            #pragma unroll
            for (int t = 0; t < 3; t++) {
                ldsm4(&bh[2 * t][0], bbase + boff[t][j]);
                ldsm4(&bl[2 * t][0], bbase + 14336 + boff[t][j]);
            }
            ldsm2(bh[6], bbase + b2off[j]);
            ldsm2(bl[6], bbase + 14336 + b2off[j]);

            #pragma unroll
            for (int mi = 0; mi < 2; mi++)
                #pragma unroll
                for (int ni = 0; ni < 7; ni++) {
                    mma16816(d[mi][ni], ah[mi], bh[ni]);
                    mma16816(d[mi][ni], ah[mi], bl[ni]);
                    mma16816(d[mi][ni], al[mi], bh[ni]);
                }
        }

        if (i + 1 < NCH) {
            const int s2 = (s ^ 1) * 16384;
            #pragma unroll
            for (int j = 0; j < 4; j++) {
                uint2 lo; uint2 hi = split_pack(pf[j], lo);
                *(uint2*)(smem + s2 + asw[j]) = hi;
                *(uint2*)(smem + s2 + 8192 + asw[j]) = lo;
            }
            cp_wait0();
        }
        __syncthreads();
    }

    // ---- epilogue: K-partial reduce through smem tile, scores + argmax + pair ----
    float* tile = (float*)smem;
    if (warpK == 0) {
        #pragma unroll
        for (int mi = 0; mi < 2; mi++)
            #pragma unroll
            for (int ni = 0; ni < 7; ni++)
                #pragma unroll
                for (int r = 0; r < 4; r++) {
                    const int row = warpM * 32 + mi * 16 + (lane >> 2) + (r >= 2 ? 8 : 0);
                    const int col = warpN * 56 + ni * 8 + (lane & 3) * 2 + (r & 1);
                    tile[row * 113 + col] = d[mi][ni][r];
                }
    }
    __syncthreads();
    if (warpK == 1) {
        #pragma unroll
        for (int mi = 0; mi < 2; mi++)
            #pragma unroll
            for (int ni = 0; ni < 7; ni++)
                #pragma unroll
                for (int r = 0; r < 4; r++) {
                    const int row = warpM * 32 + mi * 16 + (lane >> 2) + (r >= 2 ? 8 : 0);
                    const int col = warpN * 56 + ni * 8 + (lane & 3) * 2 + (r & 1);
                    tile[row * 113 + col] += d[mi][ni][r];
                }
    }
    __syncthreads();

    for (int idx = tid; idx < MC * NCLS; idx += 256) {
        const int r = idx / NCLS, c = idx - r * NCLS;
        out_scores[(size_t)(r0 + r) * NCLS + c] = tile[r * 113 + c];
    }
    if (tid < MC) {
        const int r = tid;
        float best = tile[r * 113];
        int bi = 0;
        #pragma unroll 4
        for (int c = 1; c < NCLS; c++) {
            const float v = tile[r * 113 + c];
            if (v > best) { best = v; bi = c; }
        }
        const int tg = g_tgt[r0 + r];
        g_pair[r0 + r] = (tg != bi) ? (tg | (bi << 8)) : -1;
    }
}

// ================= kernel 3a: build per-class row lists (1 CTA, deterministic) ======
__global__ __launch_bounds__(256)
void build_kernel() {
    __shared__ int scnt[32][2][NCLS];      // 25600 B
    __shared__ int s_off[2][NCLS];
    __shared__ int s_tot[2][NCLS];
    const int t = threadIdx.x;

    for (int i = t; i < 32 * 2 * NCLS; i += 256) ((int*)scnt)[i] = 0;
    __syncthreads();

    if (t < 32) {
        const int rb = t * 512;
        #pragma unroll 8
        for (int j = 0; j < 512; j++) {
            const int pr = g_pair[rb + j];
            if (pr >= 0) {
                scnt[t][0][pr & 0xFF]++;
                scnt[t][1][(pr >> 8) & 0xFF]++;
            }
        }
    }
    __syncthreads();

    if (t < 2 * NCLS) {
        const int side = t / NCLS, c = t - side * NCLS;
        int run = 0;
        #pragma unroll 4
        for (int s = 0; s < 32; s++) {
            const int v = scnt[s][side][c];
            scnt[s][side][c] = run;
            run += v;
        }
        s_tot[side][c] = run;
    }
    __syncthreads();

    if (t < 2) {
        int run = 0;
        for (int c = 0; c < NCLS; c++) { s_off[t][c] = run; run += s_tot[t][c]; }
    }
    __syncthreads();

    if (t < 2 * NCLS) {
        const int side = t / NCLS, c = t - side * NCLS;
        const int o = s_off[side][c];
        #pragma unroll 4
        for (int s = 0; s < 32; s++) scnt[s][side][c] += o;
        g_clsoff[t] = o;
        g_clscnt[t] = s_tot[side][c];
    }
    __syncthreads();

    if (t < 32) {
        const int rb = t * 512;
        for (int j = 0; j < 512; j++) {
            const int r = rb + j;
            const int pr = g_pair[r];
            if (pr >= 0) {
                g_list[scnt[t][0][pr & 0xFF]++] = r;
                g_list[NROW + scnt[t][1][(pr >> 8) & 0xFF]++] = r;
            }
        }
    }
}

// ================= kernel 3b: gather-accumulate, L2-friendly grid (R10) ==========
// blockIdx.x = (cls, side)  (200 CTAs per chunk, sharing one 84MB column slice)
// blockIdx.y = chunk        (8 chunks of 1280 cols); 5 register accums per thread.
__global__ __launch_bounds__(256)
void gather_kernel(const float* __restrict__ enc) {
    __shared__ int slist[LTILE];
    const int rest = blockIdx.x;        // 0..199
    const int cls = rest % NCLS;
    const int side = rest / NCLS;
    const int chunk = blockIdx.y;
    const int t = threadIdx.x;

    const int n = g_clscnt[side * NCLS + cls];
    const int base = g_clsoff[side * NCLS + cls];
    const int* list = g_list + side * NROW + base;
    const int c0 = chunk * CH_COLS + t;

    bool ok[5];
    #pragma unroll
    for (int k = 0; k < 5; k++) ok[k] = (c0 + k * 256) < DDIM;

    float acc[5] = {0.f, 0.f, 0.f, 0.f, 0.f};

    for (int tb = 0; tb < n; tb += LTILE) {
        const int m = (n - tb < LTILE) ? (n - tb) : LTILE;
        __syncthreads();
        for (int i = t; i < m; i += 256) slist[i] = list[tb + i];
        __syncthreads();

        int i = 0;
        for (; i + 8 <= m; i += 8) {
            int r[8];
            #pragma unroll
            for (int u = 0; u < 8; u++) r[u] = slist[i + u];
            #pragma unroll
            for (int u = 0; u < 8; u++) {
                const float* p = enc + (size_t)r[u] * DDIM + c0;
                #pragma unroll
                for (int k = 0; k < 5; k++)
                    if (ok[k]) acc[k] += __ldg(p + k * 256);
            }
        }
        for (; i < m; i++) {
            const float* p = enc + (size_t)slist[i] * DDIM + c0;
            #pragma unroll
            for (int k = 0; k < 5; k++)
                if (ok[k]) acc[k] += __ldg(p + k * 256);
        }
    }

    const size_t ob = (size_t)(side * NCLS + cls) * DDIM + c0;
    #pragma unroll
    for (int k = 0; k < 5; k++)
        if (ok[k]) g_part[ob + k * 256] = acc[k];
}

// ================= kernel 4: clip + update =================
__global__ void finalize_kernel(const float* __restrict__ ch, float* __restrict__ out2) {
    int i = blockIdx.x * blockDim.x + threadIdx.x;
    if (i >= NCLS * DDIM) return;
    float a = g_part[i];
    float s = g_part[NCLS * DDIM + i];
    a = fminf(fmaxf(a, -1.0f), 1.0f);
    s = fminf(fmaxf(s, -1.0f), 1.0f);
    out2[i] = ch[i] + a - s;
}

// ================= launch =================
extern "C" void kernel_launch(void* const* d_in, const int* in_sizes, int n_in,
                              void* d_out, int out_size) {
    (void)in_sizes; (void)n_in; (void)out_size;
    const float* enc = (const float*)d_in[0];
    const int* tgt32 = (const int*)d_in[1];
    const float* ch = (const float*)d_in[2];
    float* out = (float*)d_out;
    float* out_scores = out;                       // [N, NCLS]
    float* out_hvs = out + (size_t)NROW * NCLS;    // [NCLS, DDIM]

    cudaFuncSetAttribute(gemm_kernel, cudaFuncAttributeMaxDynamicSharedMemorySize, GEMM_SMEM);

    detect_tgt_kernel<<<1, 256>>>(tgt32);
    conv_tgt_kernel<<<(NROW + 255) / 256, 256>>>(tgt32);
    prep_b_kernel<<<(NC * KPAD + 255) / 256, 256>>>(ch);
    gemm_kernel<<<NROW / MC, 256, GEMM_SMEM>>>(enc, out_scores);
    build_kernel<<<1, 256>>>();
    gather_kernel<<<dim3(2 * NCLS, NCHK), 256>>>(enc);
    finalize_kernel<<<(NCLS * DDIM + 255) / 256, 256>>>(ch, out_hvs);
}